// round 16
// baseline (speedup 1.0000x reference)
#include <cuda_runtime.h>
#include <cstdint>

// AnchorMatcher: N anchors x M gt boxes -> packed float32 out[6N]:
//   [0,N): cls targets, [N,5N): reg targets (float4), [5N,6N): pos mask 0/1.
// Single fused kernel. Hot loop: branchless approx-IoU (MUFU.RCP) argmax
// tracking per anchor + margin-gated exact slow path for the per-gt argmax.
// Exact rounded (div.rn) semantics restored post-loop via a provable
// uniqueness margin; ambiguous anchors (rare) do an exact ascending re-scan.

#define MAXN   262144   // >= 200000
#define MAXM   128
#define POS_THR 0.5f
#define NEG_THR 0.4f
#define TPB     256
#define ADJ17   0.99999237f   // 1 - 2^-17: per-gt baseline store scale
#define AMB16   0.99998474f   // 1 - 2^-16: per-anchor ambiguity margin

// Scratch (no allocations allowed -> __device__ globals; zero-init at load)
__device__ int                g_midx[MAXN];
__device__ unsigned long long g_packed[MAXM];  // per-gt (iou_bits<<32)|(~anchor_idx)
__device__ unsigned int       g_ticket;        // last-block-done counter

__global__ __launch_bounds__(TPB) void k_iou(
    const float4* __restrict__ anchors,
    const float4* __restrict__ gts,
    const int*    __restrict__ labels,
    float*        __restrict__ out,
    int N, int M)
{
    __shared__ float4             sg[MAXM];     // gt boxes
    __shared__ float2             smeta[MAXM];  // {gt area, block approx-best*ADJ17}
    __shared__ int                slab[MAXM];   // gt labels
    __shared__ unsigned long long sp[MAXM];     // per-gt packed exact best (block)
    __shared__ bool               s_last;

    const int tid = threadIdx.x;
    if (tid < M) {
        float4 g = gts[tid];
        sg[tid]    = g;
        smeta[tid] = make_float2((g.z - g.x) * (g.w - g.y), 0.0f);
        slab[tid]  = labels[tid];
        sp[tid]    = 0ULL;
    }
    __syncthreads();

    const int  i     = blockIdx.x * TPB + tid;   // one anchor per thread
    const bool valid = (i < N);

    // Invalid threads: degenerate origin box -> inter == 0 vs every gt.
    const float4 a = valid ? anchors[i] : make_float4(0.f, 0.f, 0.f, 0.f);
    const float areaA = (a.z - a.x) * (a.w - a.y);
    const unsigned inv = 0xFFFFFFFFu - (unsigned)i;  // key low word (min-index wins)

    const unsigned sp_base = (unsigned)__cvta_generic_to_shared(sp);
    const unsigned sm_base = (unsigned)__cvta_generic_to_shared(smeta);

    float qb = 0.0f;   // approx best IoU (running max of q~)
    float qs = 0.0f;   // approx second-best
    int   bj = 0;      // approx argmax index

    #pragma unroll 4
    for (int j = 0; j < M; ++j) {
        const float4 g = sg[j];
        const float2 meta = smeta[j];            // {ga, per-gt baseline} LDS.64

        const float w = fmaxf(fminf(a.z, g.z) - fmaxf(a.x, g.x), 0.0f);
        const float h = fmaxf(fminf(a.w, g.w) - fmaxf(a.y, g.y), 0.0f);
        const float inter = w * h;
        // Same association as reference: (areaA + ga) - inter
        const float denom = (areaA + meta.x) - inter;   // > 0 always

        // Approximate IoU: MUFU.RCP + FMUL (rel err <~ 2 ulp). Branchless
        // top-2 + argmax tracking; exactness restored after the loop.
        const float qt = __fdividef(inter, denom);
        const float mn = fminf(qt, qb);
        bj = (qt > qb) ? j : bj;                 // old qb: first index on ties
        qb = fmaxf(qt, qb);
        qs = fmaxf(qs, mn);

        // Per-gt slow path: only when this lane can beat the block's approx
        // best for gt j (margin-safe: baseline is a real q~ scaled by
        // 1-2^-17 >> approx error, so the rounded winner and all min-index
        // rounded-tie holders provably fire; extras are harmless).
        if (inter > 0.0f && qt >= meta.y) {
            // exact IEEE quotient: the global per-gt argmax key must use
            // XLA's rounded value bitwise.
            const float q = __fdiv_rn(inter, denom);
            const unsigned long long key =
                ((unsigned long long)__float_as_uint(q) << 32) | inv;
            asm volatile("red.shared.max.u64 [%0], %1;"
                         :: "r"(sp_base + (unsigned)j * 8u), "l"(key) : "memory");
            const float qa = qt * ADJ17;
            if (qa > meta.y) {        // racy lower-overwrite-only: safe
                asm volatile("st.shared.f32 [%0], %1;"
                             :: "r"(sm_base + (unsigned)j * 8u + 4u), "f"(qa)
                             : "memory");
            }
        }
    }

    // ---------------- per-anchor exact resolution + epilogue ----------------
    if (valid) {
        float best = 0.0f;   // exact rounded max IoU
        int   bjf  = 0;      // exact rounded argmax (first index on ties)

        if (qb > 0.0f) {
            if (qs >= qb * AMB16) {
                // Ambiguous (rare): exact ascending re-scan reproduces
                // jnp.argmax first-index semantics literally.
                for (int j = 0; j < M; ++j) {
                    const float4 g = sg[j];
                    const float w = fmaxf(fminf(a.z, g.z) - fmaxf(a.x, g.x), 0.0f);
                    const float h = fmaxf(fminf(a.w, g.w) - fmaxf(a.y, g.y), 0.0f);
                    const float inter = w * h;
                    if (inter > 0.0f) {
                        const float denom = (areaA + smeta[j].x) - inter;
                        const float q = __fdiv_rn(inter, denom);
                        if (q > best) { best = q; bjf = j; }
                    }
                }
            } else {
                // Unique rounded argmax: gap > 2^-16 >> approx err + ulp.
                bjf = bj;
                const float4 g = sg[bjf];
                const float w = fmaxf(fminf(a.z, g.z) - fmaxf(a.x, g.x), 0.0f);
                const float h = fmaxf(fminf(a.w, g.w) - fmaxf(a.y, g.y), 0.0f);
                const float inter = w * h;
                const float denom = (areaA + smeta[bjf].x) - inter;
                best = __fdiv_rn(inter, denom);
            }
        }
        // qb == 0 -> all-zero row: best = 0, bjf = 0 (argmax of constant row).

        g_midx[i] = bjf;

        const bool pos = (best >= POS_THR);
        out[i] = pos ? (float)slab[bjf] : (best < NEG_THR ? 0.0f : -1.0f);

        float4 r = make_float4(0.0f, 0.0f, 0.0f, 0.0f);
        if (pos) {
            const float eps = 1.1920929e-7f;  // FLT_EPSILON (jnp.finfo eps)
            const float4 g = sg[bjf];
            const float aw = fmaxf(a.z - a.x, eps);
            const float ah = fmaxf(a.w - a.y, eps);
            r.x = __fdiv_rn((g.x + g.z) * 0.5f - (a.x + a.z) * 0.5f, aw);
            r.y = __fdiv_rn((g.y + g.w) * 0.5f - (a.y + a.w) * 0.5f, ah);
            r.z = logf(__fdiv_rn(g.z - g.x, aw));
            r.w = logf(__fdiv_rn(g.w - g.y, ah));
            // WEIGHTS = (1,1,1,1) -> identity multiply skipped.
        }
        reinterpret_cast<float4*>(out + N)[i] = r;  // out+N 16B-aligned (N%4==0)
        out[5 * N + i] = pos ? 1.0f : 0.0f;
    }

    // ---------------- flush per-gt partials, elect last block ----------------
    __syncthreads();
    if (tid < M) {
        const unsigned long long v = sp[tid];
        if (v) atomicMax(&g_packed[tid], v);
    }
    __threadfence();
    __syncthreads();
    if (tid == 0)
        s_last = (atomicAdd(&g_ticket, 1u) == (unsigned)(gridDim.x - 1));
    __syncthreads();

    // ---------------- last block: patch forced positives ----------------
    if (s_last) {
        __threadfence();             // acquire: see all blocks' writes
        if (tid == 0) g_ticket = 0;  // reset for next graph replay
        if (tid < M) {
            const unsigned long long v = g_packed[tid];
            g_packed[tid] = 0ULL;    // consume-and-reset for next replay

            // v==0 <=> all-zero IoU column: reference argmax picks anchor 0.
            const unsigned ai = v ? (0xFFFFFFFFu - (unsigned)(v & 0xFFFFFFFFull)) : 0u;
            if (ai < (unsigned)N) {
                const int j = g_midx[ai];
                out[ai] = (float)slab[j];

                const float eps = 1.1920929e-7f;
                const float4 av = anchors[ai];
                const float4 g  = sg[j];     // gt tile still live in this block
                const float aw = fmaxf(av.z - av.x, eps);
                const float ah = fmaxf(av.w - av.y, eps);
                float4 r;
                r.x = __fdiv_rn((g.x + g.z) * 0.5f - (av.x + av.z) * 0.5f, aw);
                r.y = __fdiv_rn((g.y + g.w) * 0.5f - (av.y + av.w) * 0.5f, ah);
                r.z = logf(__fdiv_rn(g.z - g.x, aw));
                r.w = logf(__fdiv_rn(g.w - g.y, ah));
                reinterpret_cast<float4*>(out + N)[ai] = r;

                out[5 * N + ai] = 1.0f;
            }
        }
    }
}

// ---------------------------------------------------------------------------
extern "C" void kernel_launch(void* const* d_in, const int* in_sizes, int n_in,
                              void* d_out, int out_size)
{
    const float4* anchors = (const float4*)d_in[0];
    const float4* gts     = (const float4*)d_in[1];
    const int*    labels  = (const int*)d_in[2];
    float*        out     = (float*)d_out;

    const int N = in_sizes[0] / 4;
    const int M = in_sizes[1] / 4;   // 128

    const int blocks = (N + TPB - 1) / TPB;

    k_iou<<<blocks, TPB>>>(anchors, gts, labels, out, N, M);
}